// round 1
// baseline (speedup 1.0000x reference)
#include <cuda_runtime.h>

#define T_LEN 512
#define BATCH 2048
#define DIN   128
#define HID   16
#define NG    64            // 4 gates * HID
#define FANIN 144           // DIN + HID

// Scratch (no cudaMalloc allowed): pre-activations for all (t,b): x_t @ Wx^T
__device__ float g_pre[(size_t)T_LEN * BATCH * NG];   // 256 MB
__device__ float g_Wc[DIN * NG];                      // combined x-weights, [k][n]

// ---------------- f32x2 helpers (Blackwell packed fp32 FMA) ----------------
__device__ __forceinline__ unsigned long long pk2(float v) {
    unsigned long long r;
    asm("mov.b64 %0, {%1, %1};" : "=l"(r) : "f"(v));
    return r;
}
__device__ __forceinline__ void ffma2(unsigned long long &d,
                                      unsigned long long a,
                                      unsigned long long b) {
    asm("fma.rn.f32x2 %0, %1, %2, %0;" : "+l"(d) : "l"(a), "l"(b));
}

// ---------------- kernel 0: reorganize weights -> g_Wc[k][n] ----------------
__global__ void prep_kernel(const float* __restrict__ Wf, const float* __restrict__ Wi,
                            const float* __restrict__ Wu, const float* __restrict__ Wo) {
    for (int idx = threadIdx.x; idx < DIN * NG; idx += blockDim.x) {
        int k = idx >> 6;       // 0..127
        int n = idx & 63;       // 0..63
        int g = n >> 4;         // gate: 0=f,1=i,2=u,3=o
        int kh = n & 15;        // hidden unit
        const float* W = (g == 0) ? Wf : (g == 1) ? Wi : (g == 2) ? Wu : Wo;
        g_Wc[idx] = W[kh * FANIN + k];
    }
}

// ---------------- kernel 1: pre[m][n] = x[m][:] @ Wc[:][n] ----------------
// M = T*B rows, K = 128, N = 64.  Block: 64 rows, 256 threads, 4x4 micro-tile,
// f32x2 accumulation (cols packed in pairs).
#define BM 64
__global__ __launch_bounds__(256) void gemm_kernel(const float* __restrict__ x) {
    __shared__ float As[BM][68];   // pad 68: +4-bank stagger per row
    __shared__ float Bs[64][64];

    const int tid = threadIdx.x;
    const int ty = tid >> 4;       // 0..15 -> 4 rows each
    const int tx = tid & 15;       // 0..15 -> 4 cols each
    const size_t m0 = (size_t)blockIdx.x * BM;

    unsigned long long acc[4][2];
#pragma unroll
    for (int r = 0; r < 4; r++) { acc[r][0] = 0ull; acc[r][1] = 0ull; }

    for (int kc = 0; kc < DIN; kc += 64) {
        // load A chunk: 64 rows x 64 k (coalesced, 2 rows per warp)
#pragma unroll
        for (int i = 0; i < 4; i++) {
            int idx = tid + i * 256;
            int m = idx >> 4, k4 = idx & 15;
            float4 v = *(const float4*)(x + (m0 + m) * (size_t)DIN + kc + k4 * 4);
            *(float4*)&As[m][k4 * 4] = v;
        }
        // load B chunk: 64 k x 64 n (direct copy of g_Wc rows)
#pragma unroll
        for (int i = 0; i < 4; i++) {
            int idx = tid + i * 256;
            int k = idx >> 4, n4 = idx & 15;
            *(float4*)&Bs[k][n4 * 4] = *(const float4*)(g_Wc + (size_t)(kc + k) * NG + n4 * 4);
        }
        __syncthreads();

#pragma unroll
        for (int k4 = 0; k4 < 16; k4++) {
            float4 av[4];
#pragma unroll
            for (int r = 0; r < 4; r++)
                av[r] = *(const float4*)&As[ty * 4 + r][k4 * 4];
            unsigned long long bv[4][2];
#pragma unroll
            for (int kk = 0; kk < 4; kk++) {
                ulonglong2 b2 = *(const ulonglong2*)&Bs[k4 * 4 + kk][tx * 4];
                bv[kk][0] = b2.x; bv[kk][1] = b2.y;
            }
#pragma unroll
            for (int r = 0; r < 4; r++) {
                const float* ar = (const float*)&av[r];
#pragma unroll
                for (int kk = 0; kk < 4; kk++) {
                    unsigned long long ap = pk2(ar[kk]);
                    ffma2(acc[r][0], ap, bv[kk][0]);
                    ffma2(acc[r][1], ap, bv[kk][1]);
                }
            }
        }
        __syncthreads();
    }

#pragma unroll
    for (int r = 0; r < 4; r++) {
        ulonglong2 v; v.x = acc[r][0]; v.y = acc[r][1];
        *(ulonglong2*)(g_pre + (m0 + ty * 4 + r) * (size_t)NG + tx * 4) = v;
    }
}

// ---------------- kernel 2: sequential recurrence, one warp per batch row ----
// lane = half*16 + kk.  half 0 handles gates (f, i); half 1 handles (u, o).
// Lane computes z for its two gates (h-part via shuffle-broadcast), then
// cos(z + b + theta), inclusive cumprod across the 16-lane half, nonlinearity,
// cross-half exchange, and the c/h update (valid in lanes 0-15).
__global__ __launch_bounds__(128) void recur_kernel(
    const float* __restrict__ Wf, const float* __restrict__ bfv,
    const float* __restrict__ Wi, const float* __restrict__ biv,
    const float* __restrict__ Wu, const float* __restrict__ buv,
    const float* __restrict__ Wo, const float* __restrict__ bov,
    const float* __restrict__ thf, const float* __restrict__ thi,
    const float* __restrict__ thu, const float* __restrict__ tho,
    float* __restrict__ out) {

    const int warp = blockIdx.x * (blockDim.x >> 5) + (threadIdx.x >> 5);
    const int lane = threadIdx.x & 31;
    const int half = lane >> 4;
    const int kk   = lane & 15;
    const int r    = warp;                 // batch row (0..2047)
    const unsigned FULL = 0xffffffffu;

    const float* WA = half ? Wu : Wf;      // gate A: f (half0) / u (half1)
    const float* WB = half ? Wo : Wi;      // gate B: i (half0) / o (half1)

    float wa[HID], wb[HID];
#pragma unroll
    for (int j = 0; j < HID; j++) {
        wa[j] = WA[kk * FANIN + DIN + j];
        wb[j] = WB[kk * FANIN + DIN + j];
    }
    // fold bias + theta (z only ever appears as z + theta inside cos)
    const float addA = half ? (buv[kk] + thu[kk]) : (bfv[kk] + thf[kk]);
    const float addB = half ? (bov[kk] + tho[kk]) : (biv[kk] + thi[kk]);

    float h = 0.f, c = 0.f;

    const size_t stride = (size_t)BATCH * NG;
    const float* pbase = g_pre + (size_t)r * NG + half * 32 + kk;  // gate A slot; B at +16

    float bufA[4], bufB[4];
#pragma unroll
    for (int p = 0; p < 4; p++) {
        bufA[p] = pbase[(size_t)p * stride];
        bufB[p] = pbase[(size_t)p * stride + 16];
    }

    const size_t outIdx = (size_t)r * HID + kk;

#pragma unroll 4
    for (int t = 0; t < T_LEN; t++) {
        const int slot = t & 3;
        float zA = bufA[slot] + addA;
        float zB = bufB[slot] + addB;
        if (t + 4 < T_LEN) {   // depth-4 prefetch to keep DRAM MLP up
            bufA[slot] = pbase[(size_t)(t + 4) * stride];
            bufB[slot] = pbase[(size_t)(t + 4) * stride + 16];
        }
        // recurrent part of the dot product: h lives in lanes 0..15
#pragma unroll
        for (int j = 0; j < HID; j++) {
            float hj = __shfl_sync(FULL, h, j);
            zA = fmaf(hj, wa[j], zA);
            zB = fmaf(hj, wb[j], zB);
        }
        float pA = __cosf(zA);
        float pB = __cosf(zB);
        // inclusive cumprod over the 16-lane half (kk guard isolates halves)
#pragma unroll
        for (int d = 1; d < 16; d <<= 1) {
            float uA = __shfl_up_sync(FULL, pA, d);
            float uB = __shfl_up_sync(FULL, pB, d);
            if (kk >= d) { pA *= uA; pB *= uB; }
        }
        // nonlinearity: half0 -> (sigmoid, sigmoid); half1 -> (tanh, sigmoid)
        // shared exp/rcp form, no divergence:
        float scl = half ? 2.f : 1.f;
        float eA = __expf(scl * pA);
        float qA = __fdividef(1.f, eA + 1.f);
        float sA = half ? (1.f - 2.f * qA) : (1.f - qA);
        float eB = __expf(pB);
        float sB = 1.f - __fdividef(1.f, eB + 1.f);
        // exchange across halves: lanes<16 receive g=tanh(u) and o
        float gx = __shfl_xor_sync(FULL, sA, 16);
        float ox = __shfl_xor_sync(FULL, sB, 16);
        // c/h update (meaningful in lanes 0..15: sA=f, sB=i, gx=g, ox=o)
        c = fmaf(sA, c, sB * gx);
        float e2 = __expf(2.f * c);
        float tc = 1.f - __fdividef(2.f, e2 + 1.f);   // tanh(c), Inf-safe
        h = ox * tc;
        if (!half)
            out[(size_t)t * (BATCH * HID) + outIdx] = h;
    }
    if (!half) {
        const size_t off = (size_t)T_LEN * BATCH * HID;
        out[off + outIdx] = h;                               // hx
        out[off + (size_t)BATCH * HID + outIdx] = c;         // cx
    }
}

// ---------------- launch ----------------
extern "C" void kernel_launch(void* const* d_in, const int* in_sizes, int n_in,
                              void* d_out, int out_size) {
    const float* x   = (const float*)d_in[0];
    const float* Wf  = (const float*)d_in[1];
    const float* bfv = (const float*)d_in[2];
    const float* Wi  = (const float*)d_in[3];
    const float* biv = (const float*)d_in[4];
    const float* Wu  = (const float*)d_in[5];
    const float* buv = (const float*)d_in[6];
    const float* Wo  = (const float*)d_in[7];
    const float* bov = (const float*)d_in[8];
    const float* thf = (const float*)d_in[9];
    const float* thi = (const float*)d_in[10];
    const float* thu = (const float*)d_in[11];
    const float* tho = (const float*)d_in[12];
    float* out = (float*)d_out;

    prep_kernel<<<1, 256>>>(Wf, Wi, Wu, Wo);
    gemm_kernel<<<(T_LEN * BATCH) / BM, 256>>>(x);
    recur_kernel<<<BATCH / 4, 128>>>(Wf, bfv, Wi, biv, Wu, buv, Wo, bov,
                                     thf, thi, thu, tho, out);
}

// round 6
// speedup vs baseline: 1.2561x; 1.2561x over previous
#include <cuda_runtime.h>
#include <cstdint>

#define T_LEN 512
#define BATCH 2048
#define DIN   128
#define HID   16
#define NG    64            // 4 gates * HID
#define FANIN 144           // DIN + HID

// Scratch: pre-activations x @ Wx^T for all (t,b); bf16 hi/lo weight tiles.
__device__ float g_pre[(size_t)T_LEN * BATCH * NG];     // 256 MB
__device__ unsigned char g_Bh[NG * DIN * 2];            // B hi, [n][k] row-major bf16
__device__ unsigned char g_Bl[NG * DIN * 2];            // B lo, [n][k] row-major bf16

// ======================= helpers =======================
__device__ __forceinline__ uint32_t smem_u32(const void* p) {
    uint32_t a;
    asm("{ .reg .u64 t; cvta.to.shared.u64 t, %1; cvt.u32.u64 %0, t; }" : "=r"(a) : "l"(p));
    return a;
}
// cvt pair: LOWER half = first value argument
#define CVT2(result, a, b) \
    asm("cvt.rn.satfinite.bf16x2.f32 %0, %1, %2;" : "=r"(result) : "f"(b), "f"(a))

#define LDMX4(r0, r1, r2, r3, addr) \
    asm volatile("ldmatrix.sync.aligned.m8n8.x4.shared.b16 {%0,%1,%2,%3}, [%4];" \
        : "=r"(r0), "=r"(r1), "=r"(r2), "=r"(r3) : "r"(addr))

#define MMA16816(c0, c1, c2, c3, a0, a1, a2, a3, b0, b1) \
    asm volatile("mma.sync.aligned.m16n8k16.row.col.f32.bf16.bf16.f32 " \
        "{%0,%1,%2,%3}, {%4,%5,%6,%7}, {%8,%9}, {%0,%1,%2,%3};" \
        : "+f"(c0), "+f"(c1), "+f"(c2), "+f"(c3) \
        : "r"(a0), "r"(a1), "r"(a2), "r"(a3), "r"(b0), "r"(b1))

// ---------------- kernel 0: build bf16 hi/lo B tiles, [n][k] row-major ------
__global__ void prep_kernel(const float* __restrict__ Wf, const float* __restrict__ Wi,
                            const float* __restrict__ Wu, const float* __restrict__ Wo) {
    int idx = blockIdx.x * blockDim.x + threadIdx.x;
    if (idx >= NG * DIN) return;
    int n = idx >> 7;          // 0..63 (output col: gate*16 + kh)
    int k = idx & 127;         // 0..127
    int g = n >> 4, kh = n & 15;
    const float* W = (g == 0) ? Wf : (g == 1) ? Wi : (g == 2) ? Wu : Wo;
    float w = W[kh * FANIN + k];
    uint32_t hp; CVT2(hp, w, 0.f);
    float hf = __uint_as_float(hp << 16);
    uint32_t lp; CVT2(lp, w - hf, 0.f);
    *(unsigned short*)(g_Bh + (size_t)idx * 2) = (unsigned short)(hp & 0xffffu);
    *(unsigned short*)(g_Bl + (size_t)idx * 2) = (unsigned short)(lp & 0xffffu);
}

// ---------------- kernel 1: HMMA split-bf16 GEMM ----------------
// pre[m][n] = x[m][:] @ B[n][:]^T ; block tile M=128, N=64, K=128; 4 warps.
// D = Ah*Bh + Ah*Bl + Al*Bh (fp32 accum) ~ fp32 precision.
// smem rows padded to 272 B (68 words) -> conflict-free ldmatrix.
#define PADB 272
#define SM_AH 0
#define SM_AL 34816
#define SM_BH 69632
#define SM_BL 87040
#define GEMM_SMEM 104448

__global__ __launch_bounds__(128) void gemm_mma_kernel(const float* __restrict__ x) {
    extern __shared__ char smem[];
    const uint32_t sb = smem_u32(smem);
    const int tid = threadIdx.x;
    const int wid = tid >> 5;
    const int lane = tid & 31;
    const size_t m0 = (size_t)blockIdx.x * 128;

    // ---- stage B (hi/lo) into padded smem rows: 64 rows x 256 B each ----
    {
        const uint2* bhs = (const uint2*)g_Bh;
        const uint2* bls = (const uint2*)g_Bl;
#pragma unroll
        for (int i = tid; i < 2048; i += 128) {
            int row = i >> 5, ch = i & 31;       // 32 x 8B chunks per row
            uint32_t off = row * PADB + ch * 8;
            *(uint2*)(smem + SM_BH + off) = bhs[i];
            *(uint2*)(smem + SM_BL + off) = bls[i];
        }
    }

    // ---- stage A: fp32 -> bf16 hi/lo split into padded smem rows ----
    {
        const float4* xv = (const float4*)(x + m0 * DIN);
#pragma unroll 4
        for (int i = tid; i < 4096; i += 128) {
            int row = i >> 5;                    // 32 float4 per 128-float row
            int c4  = i & 31;
            float4 v = xv[i];
            uint32_t h01, h23, l01, l23;
            CVT2(h01, v.x, v.y);
            CVT2(h23, v.z, v.w);
            float hx = __uint_as_float(h01 << 16);
            float hy = __uint_as_float(h01 & 0xffff0000u);
            float hz = __uint_as_float(h23 << 16);
            float hw = __uint_as_float(h23 & 0xffff0000u);
            CVT2(l01, v.x - hx, v.y - hy);
            CVT2(l23, v.z - hz, v.w - hw);
            uint32_t off = row * PADB + c4 * 8;
            *(uint2*)(smem + SM_AH + off) = make_uint2(h01, h23);
            *(uint2*)(smem + SM_AL + off) = make_uint2(l01, l23);
        }
    }
    __syncthreads();

    // ---- mainloop: K = 8 steps of 16; 3 passes fused per step ----
    float acc[2][8][4];
#pragma unroll
    for (int mt = 0; mt < 2; mt++)
#pragma unroll
        for (int nt = 0; nt < 8; nt++)
#pragma unroll
            for (int q = 0; q < 4; q++) acc[mt][nt][q] = 0.f;

    // shared lane-address pattern for both A m-tiles and B n-pairs:
    // row_in_tile = lane & 15, k_half = lane >> 4  (8 cols)
    const int rsel = lane & 15;
    const int ksel = (lane >> 4) * 16;           // byte offset of 8-col half

#pragma unroll
    for (int ks = 0; ks < 8; ks++) {
        const uint32_t kbyte = ks * 32 + ksel;   // 16 k * 2B = 32B per step
        uint32_t ah[2][4], al[2][4];
#pragma unroll
        for (int mt = 0; mt < 2; mt++) {
            uint32_t rowb = (wid * 32 + mt * 16 + rsel) * PADB + kbyte;
            LDMX4(ah[mt][0], ah[mt][1], ah[mt][2], ah[mt][3], sb + SM_AH + rowb);
            LDMX4(al[mt][0], al[mt][1], al[mt][2], al[mt][3], sb + SM_AL + rowb);
        }
        uint32_t bh[4][4], bl[4][4];
#pragma unroll
        for (int np = 0; np < 4; np++) {
            uint32_t rowb = (np * 16 + rsel) * PADB + kbyte;
            LDMX4(bh[np][0], bh[np][1], bh[np][2], bh[np][3], sb + SM_BH + rowb);
            LDMX4(bl[np][0], bl[np][1], bl[np][2], bl[np][3], sb + SM_BL + rowb);
        }
        // frag regs from x4 load: {n0k0, n1k0, n0k1, n1k1}
#pragma unroll
        for (int mt = 0; mt < 2; mt++) {
#pragma unroll
            for (int np = 0; np < 4; np++) {
#pragma unroll
                for (int o = 0; o < 2; o++) {
                    float* c = acc[mt][np * 2 + o];
                    // pass 1: Ah * Bh
                    MMA16816(c[0], c[1], c[2], c[3],
                             ah[mt][0], ah[mt][1], ah[mt][2], ah[mt][3],
                             bh[np][o], bh[np][o + 2]);
                    // pass 2: Ah * Bl
                    MMA16816(c[0], c[1], c[2], c[3],
                             ah[mt][0], ah[mt][1], ah[mt][2], ah[mt][3],
                             bl[np][o], bl[np][o + 2]);
                    // pass 3: Al * Bh
                    MMA16816(c[0], c[1], c[2], c[3],
                             al[mt][0], al[mt][1], al[mt][2], al[mt][3],
                             bh[np][o], bh[np][o + 2]);
                }
            }
        }
    }

    // ---- epilogue: c-frag -> g_pre ----
    // c0,c1 -> row = base + lane/4, cols n + (lane&3)*2 ; c2,c3 -> row+8
    const int rq = lane >> 2;
    const int cq = (lane & 3) * 2;
#pragma unroll
    for (int mt = 0; mt < 2; mt++) {
        size_t row = m0 + wid * 32 + mt * 16 + rq;
#pragma unroll
        for (int nt = 0; nt < 8; nt++) {
            float* c = acc[mt][nt];
            int col = nt * 8 + cq;
            *(float2*)(g_pre + row * NG + col)       = make_float2(c[0], c[1]);
            *(float2*)(g_pre + (row + 8) * NG + col) = make_float2(c[2], c[3]);
        }
    }
}

// ---------------- kernel 2: sequential recurrence, one warp per batch row ----
// (unchanged from the passing round-1 kernel)
__global__ __launch_bounds__(128) void recur_kernel(
    const float* __restrict__ Wf, const float* __restrict__ bfv,
    const float* __restrict__ Wi, const float* __restrict__ biv,
    const float* __restrict__ Wu, const float* __restrict__ buv,
    const float* __restrict__ Wo, const float* __restrict__ bov,
    const float* __restrict__ thf, const float* __restrict__ thi,
    const float* __restrict__ thu, const float* __restrict__ tho,
    float* __restrict__ out) {

    const int warp = blockIdx.x * (blockDim.x >> 5) + (threadIdx.x >> 5);
    const int lane = threadIdx.x & 31;
    const int half = lane >> 4;
    const int kk   = lane & 15;
    const int r    = warp;
    const unsigned FULL = 0xffffffffu;

    const float* WA = half ? Wu : Wf;
    const float* WB = half ? Wo : Wi;

    float wa[HID], wb[HID];
#pragma unroll
    for (int j = 0; j < HID; j++) {
        wa[j] = WA[kk * FANIN + DIN + j];
        wb[j] = WB[kk * FANIN + DIN + j];
    }
    const float addA = half ? (buv[kk] + thu[kk]) : (bfv[kk] + thf[kk]);
    const float addB = half ? (bov[kk] + tho[kk]) : (biv[kk] + thi[kk]);

    float h = 0.f, c = 0.f;

    const size_t stride = (size_t)BATCH * NG;
    const float* pbase = g_pre + (size_t)r * NG + half * 32 + kk;

    float bufA[4], bufB[4];
#pragma unroll
    for (int p = 0; p < 4; p++) {
        bufA[p] = pbase[(size_t)p * stride];
        bufB[p] = pbase[(size_t)p * stride + 16];
    }

    const size_t outIdx = (size_t)r * HID + kk;

#pragma unroll 4
    for (int t = 0; t < T_LEN; t++) {
        const int slot = t & 3;
        float zA = bufA[slot] + addA;
        float zB = bufB[slot] + addB;
        if (t + 4 < T_LEN) {
            bufA[slot] = pbase[(size_t)(t + 4) * stride];
            bufB[slot] = pbase[(size_t)(t + 4) * stride + 16];
        }
#pragma unroll
        for (int j = 0; j < HID; j++) {
            float hj = __shfl_sync(FULL, h, j);
            zA = fmaf(hj, wa[j], zA);
            zB = fmaf(hj, wb[j], zB);
        }
        float pA = __cosf(zA);
        float pB = __cosf(zB);
#pragma unroll
        for (int d = 1; d < 16; d <<= 1) {
            float uA = __shfl_up_sync(FULL, pA, d);
            float uB = __shfl_up_sync(FULL, pB, d);
            if (kk >= d) { pA *= uA; pB *= uB; }
        }
        float scl = half ? 2.f : 1.f;
        float eA = __expf(scl * pA);
        float qA = __fdividef(1.f, eA + 1.f);
        float sA = half ? (1.f - 2.f * qA) : (1.f - qA);
        float eB = __expf(pB);
        float sB = 1.f - __fdividef(1.f, eB + 1.f);
        float gx = __shfl_xor_sync(FULL, sA, 16);
        float ox = __shfl_xor_sync(FULL, sB, 16);
        c = fmaf(sA, c, sB * gx);
        float e2 = __expf(2.f * c);
        float tc = 1.f - __fdividef(2.f, e2 + 1.f);
        h = ox * tc;
        if (!half)
            out[(size_t)t * (BATCH * HID) + outIdx] = h;
    }
    if (!half) {
        const size_t off = (size_t)T_LEN * BATCH * HID;
        out[off + outIdx] = h;
        out[off + (size_t)BATCH * HID + outIdx] = c;
    }
}

// ---------------- launch ----------------
extern "C" void kernel_launch(void* const* d_in, const int* in_sizes, int n_in,
                              void* d_out, int out_size) {
    const float* x   = (const float*)d_in[0];
    const float* Wf  = (const float*)d_in[1];
    const float* bfv = (const float*)d_in[2];
    const float* Wi  = (const float*)d_in[3];
    const float* biv = (const float*)d_in[4];
    const float* Wu  = (const float*)d_in[5];
    const float* buv = (const float*)d_in[6];
    const float* Wo  = (const float*)d_in[7];
    const float* bov = (const float*)d_in[8];
    const float* thf = (const float*)d_in[9];
    const float* thi = (const float*)d_in[10];
    const float* thu = (const float*)d_in[11];
    const float* tho = (const float*)d_in[12];
    float* out = (float*)d_out;

    cudaFuncSetAttribute(gemm_mma_kernel, cudaFuncAttributeMaxDynamicSharedMemorySize, GEMM_SMEM);

    prep_kernel<<<16, 512>>>(Wf, Wi, Wu, Wo);
    gemm_mma_kernel<<<(T_LEN * BATCH) / 128, 128, GEMM_SMEM>>>(x);
    recur_kernel<<<BATCH / 4, 128>>>(Wf, bfv, Wi, biv, Wu, buv, Wo, bov,
                                     thf, thi, thu, tho, out);
}